// round 6
// baseline (speedup 1.0000x reference)
#include <cuda_runtime.h>
#include <cstdint>

#define B_  4
#define S_  2048
#define D_  256
#define NH_ 12

// fp32 scratch for projected QK and V, layout [b][n][f][d]  (100 MB each)
__device__ float g_qk[(size_t)B_ * NH_ * S_ * D_];
__device__ float g_v [(size_t)B_ * NH_ * S_ * D_];

// ---------------- packed f32x2 helpers (Blackwell FFMA2 path) ----------------
__device__ __forceinline__ unsigned long long ffma2(unsigned long long a,
                                                    unsigned long long b,
                                                    unsigned long long c) {
    unsigned long long d;
    asm("fma.rn.f32x2 %0, %1, %2, %3;" : "=l"(d) : "l"(a), "l"(b), "l"(c));
    return d;
}
__device__ __forceinline__ unsigned long long fmul2(unsigned long long a,
                                                    unsigned long long b) {
    unsigned long long d;
    asm("mul.rn.f32x2 %0, %1, %2;" : "=l"(d) : "l"(a), "l"(b));
    return d;
}
__device__ __forceinline__ unsigned long long fpack2(float lo, float hi) {
    unsigned long long d;
    asm("mov.b64 %0, {%1, %2};" : "=l"(d) : "f"(lo), "f"(hi));
    return d;
}
__device__ __forceinline__ float2 funpack2(unsigned long long v) {
    float lo, hi;
    asm("mov.b64 {%0, %1}, %2;" : "=f"(lo), "=f"(hi) : "l"(v));
    return make_float2(lo, hi);
}

// ---------------- projection: [8192,256] x [256,3072] (+bias), x2 ----------------
__global__ __launch_bounds__(256, 2)
void proj_kernel(const float* __restrict__ X,
                 const float* __restrict__ Wqk, const float* __restrict__ bqk,
                 const float* __restrict__ Wv,  const float* __restrict__ bvp)
{
    const float* W    = (blockIdx.z == 0) ? Wqk : Wv;
    const float* bias = (blockIdx.z == 0) ? bqk : bvp;
    float* Out        = (blockIdx.z == 0) ? g_qk : g_v;

    __shared__ float As[8][128];
    __shared__ float Bs[8][128];

    const int t  = threadIdx.x;
    const int tx = t & 15, ty = t >> 4;
    const int m0 = blockIdx.y * 128;
    const int c0 = blockIdx.x * 128;

    unsigned long long acc[8][4];
#pragma unroll
    for (int i = 0; i < 8; i++)
#pragma unroll
        for (int j = 0; j < 4; j++) acc[i][j] = 0ull;

    const int lm = t >> 1;
    const int lk = (t & 1) * 4;
    const int brow = t >> 5;
    const int bcol = (t & 31) * 4;

    for (int k0 = 0; k0 < 256; k0 += 8) {
        float4 xa = *(const float4*)&X[(size_t)(m0 + lm) * 256 + k0 + lk];
        float4 wb = *(const float4*)&W[(size_t)(k0 + brow) * 3072 + c0 + bcol];
        __syncthreads();
        As[lk + 0][lm] = xa.x; As[lk + 1][lm] = xa.y;
        As[lk + 2][lm] = xa.z; As[lk + 3][lm] = xa.w;
        *(float4*)&Bs[brow][bcol] = wb;
        __syncthreads();
#pragma unroll
        for (int kk = 0; kk < 8; kk++) {
            float a[8];
            *(float4*)&a[0] = *(const float4*)&As[kk][ty * 8];
            *(float4*)&a[4] = *(const float4*)&As[kk][ty * 8 + 4];
            ulonglong2 b01 = *(const ulonglong2*)&Bs[kk][tx * 8];
            ulonglong2 b23 = *(const ulonglong2*)&Bs[kk][tx * 8 + 4];
            unsigned long long bp[4] = {b01.x, b01.y, b23.x, b23.y};
#pragma unroll
            for (int i = 0; i < 8; i++) {
                unsigned long long ap = fpack2(a[i], a[i]);
#pragma unroll
                for (int j = 0; j < 4; j++) acc[i][j] = ffma2(ap, bp[j], acc[i][j]);
            }
        }
    }

#pragma unroll
    for (int j = 0; j < 4; j++) {
        int col = c0 + tx * 8 + 2 * j;
        float2 bb = *(const float2*)&bias[col];
        int nh = col >> 8, d = col & 255;
#pragma unroll
        for (int i = 0; i < 8; i++) {
            int m = m0 + ty * 8 + i;
            int bb_ = m >> 11, f = m & 2047;
            float2 v = funpack2(acc[i][j]);
            v.x += bb.x; v.y += bb.y;
            *(float2*)&Out[(((size_t)bb_ * NH_ + nh) * S_ + f) * D_ + d] = v;
        }
    }
}

// ---------------- flash attention v2: QT=128, shared KV buffer, swizzled smem ----------------
#define QT 128
#define KT 64
#define SP 65   // score tile row stride (floats)

__global__ __launch_bounds__(256, 1)
void attn_kernel(const float* __restrict__ X, const int* __restrict__ mask,
                 float* __restrict__ out)
{
    extern __shared__ float sm[];
    float* Qs   = sm;                          // [128][256] chunk-swizzled
    float* KVs  = Qs + QT * 256;               // [64][256]  chunk-swizzled (K then V)
    float* Ss   = KVs + KT * 256;              // [128][SP]
    float* m_sm = Ss + QT * SP;                // [128]
    float* l_sm = m_sm + QT;                   // [128]
    float* sc_sm= l_sm + QT;                   // [128]

    const int t  = threadIdx.x;
    const int q0 = blockIdx.x * QT;
    const int nh = blockIdx.y;
    const int bb = blockIdx.z;

    // ---- load Q tile once (swizzle: chunk' = chunk ^ ((row>>2)&7)) ----
    {
        const int qrow = t >> 1;
        const int qcb  = (t & 1) * 32;
        const int qswz = (qrow >> 2) & 7;
        const float* srcQ = X + ((size_t)bb * S_ + q0 + qrow) * D_;
        float* dst = &Qs[qrow * 256];
#pragma unroll
        for (int ii = 0; ii < 8; ii++) {
            float4 tmp[4];
#pragma unroll
            for (int u = 0; u < 4; u++)
                tmp[u] = *(const float4*)&srcQ[(qcb + ii * 4 + u) * 4];
#pragma unroll
            for (int u = 0; u < 4; u++) {
                int c = qcb + ii * 4 + u;
                *(float4*)&dst[(c ^ qswz) << 2] = tmp[u];
            }
        }
    }
    if (t < QT) { m_sm[t] = -3.4e38f; l_sm[t] = 0.0f; }

    // O accumulators: q = (t&15)+16i, d-pair = (t>>4)+16j
    unsigned long long o2[8][8];
#pragma unroll
    for (int i = 0; i < 8; i++)
#pragma unroll
        for (int j = 0; j < 8; j++) o2[i][j] = 0ull;

    const float* gK = g_qk + (size_t)(bb * NH_ + nh) * S_ * D_;
    const float* gV = g_v  + (size_t)(bb * NH_ + nh) * S_ * D_;
    const int*   gM = mask + (size_t)bb * S_ * S_;

    // per-thread maps
    const int qg = t >> 3;            // 0..31  (S-phase q group)
    const int tx = t & 7;             // 0..7   (S-phase k lane)
    const int qsw = qg & 7;
    const int lrow = t >> 2;          // 0..63  (tile load row)
    const int lcb  = (t & 3) * 16;    // tile load chunk base
    const int lsw  = lrow & 7;
    const int qi = t & 15;            // O-phase q lane
    const int dg = t >> 4;            // O-phase d-pair group 0..15
    const int dhalf = dg >> 1;
    const int dbit  = (dg & 1) << 1;

    for (int kt = 0; kt < S_ / KT; kt++) {
        const int f0 = kt * KT;
        __syncthreads();                          // (A) prev O done, KV buffer free
        // ---- load K tile ----
        {
            const float* srcK = gK + (size_t)(f0 + lrow) * D_;
            float* dst = &KVs[lrow * 256];
#pragma unroll
            for (int ii = 0; ii < 4; ii++) {
                float4 tmp[4];
#pragma unroll
                for (int u = 0; u < 4; u++)
                    tmp[u] = *(const float4*)&srcK[(lcb + ii * 4 + u) * 4];
#pragma unroll
                for (int u = 0; u < 4; u++) {
                    int c = lcb + ii * 4 + u;
                    *(float4*)&dst[(c ^ lsw) << 2] = tmp[u];
                }
            }
        }
        __syncthreads();                          // (B) K ready
        // ---- S phase: two j-halves to cap register pressure ----
        {
            const float* qp0 = &Qs[(qg * 4 + 0) * 256];
            const float* qp1 = &Qs[(qg * 4 + 1) * 256];
            const float* qp2 = &Qs[(qg * 4 + 2) * 256];
            const float* qp3 = &Qs[(qg * 4 + 3) * 256];
#pragma unroll
            for (int half = 0; half < 2; half++) {
                unsigned long long acc[4][4];
#pragma unroll
                for (int i = 0; i < 4; i++)
#pragma unroll
                    for (int j = 0; j < 4; j++) acc[i][j] = 0ull;
#pragma unroll 4
                for (int d4 = 0; d4 < 64; d4++) {
                    const int qoff = (d4 ^ qsw) << 2;
                    const int koff = (d4 ^ tx) << 2;
                    ulonglong2 qv0 = *(const ulonglong2*)(qp0 + qoff);
                    ulonglong2 qv1 = *(const ulonglong2*)(qp1 + qoff);
                    ulonglong2 qv2 = *(const ulonglong2*)(qp2 + qoff);
                    ulonglong2 qv3 = *(const ulonglong2*)(qp3 + qoff);
#pragma unroll
                    for (int j = 0; j < 4; j++) {
                        int k = tx + 8 * (half * 4 + j);
                        ulonglong2 kv = *(const ulonglong2*)&KVs[k * 256 + koff];
                        acc[0][j] = ffma2(qv0.x, kv.x, acc[0][j]);
                        acc[0][j] = ffma2(qv0.y, kv.y, acc[0][j]);
                        acc[1][j] = ffma2(qv1.x, kv.x, acc[1][j]);
                        acc[1][j] = ffma2(qv1.y, kv.y, acc[1][j]);
                        acc[2][j] = ffma2(qv2.x, kv.x, acc[2][j]);
                        acc[2][j] = ffma2(qv2.y, kv.y, acc[2][j]);
                        acc[3][j] = ffma2(qv3.x, kv.x, acc[3][j]);
                        acc[3][j] = ffma2(qv3.y, kv.y, acc[3][j]);
                    }
                }
                // scores + mask -> Ss
#pragma unroll
                for (int i = 0; i < 4; i++) {
                    int q = qg * 4 + i;
#pragma unroll
                    for (int j = 0; j < 4; j++) {
                        int k = tx + 8 * (half * 4 + j);
                        float2 p = funpack2(acc[i][j]);
                        float s = p.x + p.y;
                        int mv = gM[(size_t)(q0 + q) * S_ + f0 + k];
                        s += (1.0f - (float)mv) * -10000.0f;
                        Ss[q * SP + k] = s;
                    }
                }
            }
        }
        __syncthreads();                          // (C) Ss complete, K reads done
        // ---- load V tile (overwrites K buffer) — LDG latency hides under softmax ----
        {
            const float* srcV = gV + (size_t)(f0 + lrow) * D_;
            float* dst = &KVs[lrow * 256];
#pragma unroll
            for (int ii = 0; ii < 4; ii++) {
                float4 tmp[4];
#pragma unroll
                for (int u = 0; u < 4; u++)
                    tmp[u] = *(const float4*)&srcV[(lcb + ii * 4 + u) * 4];
#pragma unroll
                for (int u = 0; u < 4; u++) {
                    int c = lcb + ii * 4 + u;
                    *(float4*)&dst[(c ^ lsw) << 2] = tmp[u];
                }
            }
        }
        // ---- online softmax (disjoint memory from V load; no sync needed) ----
        {
            const int r = t >> 1, seg = t & 1;
            float* srow = &Ss[r * SP + seg * 32];
            float mloc = -3.4e38f;
#pragma unroll
            for (int cc = 0; cc < 32; cc++) mloc = fmaxf(mloc, srow[cc]);
            mloc = fmaxf(mloc, __shfl_xor_sync(0xffffffffu, mloc, 1));
            float mold = m_sm[r];
            float mnew = fmaxf(mold, mloc);
            float lsum = 0.0f;
#pragma unroll
            for (int cc = 0; cc < 32; cc++) {
                float p = __expf(srow[cc] - mnew);
                srow[cc] = p;
                lsum += p;
            }
            lsum += __shfl_xor_sync(0xffffffffu, lsum, 1);
            if (seg == 0) {
                float sc = __expf(mold - mnew);
                sc_sm[r] = sc;
                l_sm[r]  = l_sm[r] * sc + lsum;
                m_sm[r]  = mnew;
            }
        }
        __syncthreads();                          // (D) V ready + softmax done
        // ---- O phase: rescale + O += P·V ----
        {
#pragma unroll
            for (int i = 0; i < 8; i++) {
                float sc = sc_sm[qi + 16 * i];
                unsigned long long sc2 = fpack2(sc, sc);
#pragma unroll
                for (int j = 0; j < 8; j++) o2[i][j] = fmul2(sc2, o2[i][j]);
            }
#pragma unroll 2
            for (int k = 0; k < KT; k++) {
                unsigned long long p2[8];
#pragma unroll
                for (int i = 0; i < 8; i++) {
                    float p = Ss[(qi + 16 * i) * SP + k];
                    p2[i] = fpack2(p, p);
                }
                const int ksw = k & 7;
                const float* vrow = &KVs[k * 256];
#pragma unroll
                for (int j = 0; j < 8; j++) {
                    int off = (((dhalf + 8 * j) ^ ksw) << 2) + dbit;
                    unsigned long long v2 = *(const unsigned long long*)&vrow[off];
                    o2[0][j] = ffma2(p2[0], v2, o2[0][j]);
                    o2[1][j] = ffma2(p2[1], v2, o2[1][j]);
                    o2[2][j] = ffma2(p2[2], v2, o2[2][j]);
                    o2[3][j] = ffma2(p2[3], v2, o2[3][j]);
                    o2[4][j] = ffma2(p2[4], v2, o2[4][j]);
                    o2[5][j] = ffma2(p2[5], v2, o2[5][j]);
                    o2[6][j] = ffma2(p2[6], v2, o2[6][j]);
                    o2[7][j] = ffma2(p2[7], v2, o2[7][j]);
                }
            }
        }
    }
    // ---- epilogue: divide by l, head-sum into out via float2 atomics ----
#pragma unroll
    for (int i = 0; i < 8; i++) {
        int q = qi + 16 * i;
        float inv = 1.0f / l_sm[q];
#pragma unroll
        for (int j = 0; j < 8; j++) {
            float2 v = funpack2(o2[i][j]);
            v.x *= inv; v.y *= inv;
            atomicAdd((float2*)&out[((size_t)bb * S_ + q0 + q) * D_ + 2 * (dg + 16 * j)], v);
        }
    }
}

// ---------------- launch ----------------
extern "C" void kernel_launch(void* const* d_in, const int* in_sizes, int n_in,
                              void* d_out, int out_size)
{
    (void)in_sizes; (void)n_in;
    const float* X   = (const float*)d_in[0];
    const int*   msk = (const int*)  d_in[1];
    const float* Wqk = (const float*)d_in[2];
    const float* bqk = (const float*)d_in[3];
    const float* Wv  = (const float*)d_in[4];
    const float* bv  = (const float*)d_in[5];
    float* out = (float*)d_out;

    cudaMemsetAsync(out, 0, (size_t)out_size * sizeof(float), 0);

    dim3 pg(3072 / 128, (B_ * S_) / 128, 2);
    proj_kernel<<<pg, 256>>>(X, Wqk, bqk, Wv, bv);

    const int smem_bytes =
        (QT * 256 + KT * 256 + QT * SP + 3 * QT) * (int)sizeof(float);  // 231424
    cudaFuncSetAttribute(attn_kernel,
                         cudaFuncAttributeMaxDynamicSharedMemorySize, smem_bytes);
    dim3 ag(S_ / QT, NH_, B_);
    attn_kernel<<<ag, 256, smem_bytes>>>(X, msk, out);
}